// round 1
// baseline (speedup 1.0000x reference)
#include <cuda_runtime.h>
#include <math.h>

#define BATCH 4
#define SEQ   2048
#define DM    1024
#define NH    16
#define HD    64
#define MROWS (BATCH*SEQ)

// Scratch (device-global; no allocation allowed)
__device__ float g_q[MROWS*DM];
__device__ float g_k[MROWS*DM];
__device__ float g_v[MROWS*DM];
__device__ float g_att[MROWS*DM];

// ---------------------------------------------------------------------------
// GEMM: C[M,N] = A[M,K] @ W[N,K]^T + bias[N]
// 128x128 tile, BK=16, 256 threads, 8x8 per-thread microtile.
// ---------------------------------------------------------------------------
__global__ __launch_bounds__(256) void sgemm_bias(
    const float* __restrict__ A, const float* __restrict__ W,
    const float* __restrict__ bias, float* __restrict__ C,
    int M, int N, int K)
{
    __shared__ float As[16][128];
    __shared__ float Bs[16][128];

    const int tid = threadIdx.x;
    const int tr = tid >> 4;    // 0..15
    const int tc = tid & 15;    // 0..15
    const int rowBase = blockIdx.y * 128;
    const int colBase = blockIdx.x * 128;
    const float* Ab = A + (size_t)rowBase * K;
    const float* Wb = W + (size_t)colBase * K;

    float acc[8][8];
#pragma unroll
    for (int i = 0; i < 8; i++)
#pragma unroll
        for (int j = 0; j < 8; j++) acc[i][j] = 0.f;

    for (int k0 = 0; k0 < K; k0 += 16) {
#pragma unroll
        for (int t = 0; t < 2; t++) {
            int idx = tid + t * 256;        // 0..511
            int row = idx >> 2;             // 0..127
            int k4  = (idx & 3) << 2;       // 0,4,8,12
            float4 av = *(const float4*)(Ab + (size_t)row * K + k0 + k4);
            As[k4+0][row] = av.x; As[k4+1][row] = av.y;
            As[k4+2][row] = av.z; As[k4+3][row] = av.w;
            float4 wv = *(const float4*)(Wb + (size_t)row * K + k0 + k4);
            Bs[k4+0][row] = wv.x; Bs[k4+1][row] = wv.y;
            Bs[k4+2][row] = wv.z; Bs[k4+3][row] = wv.w;
        }
        __syncthreads();

#pragma unroll
        for (int kk = 0; kk < 16; kk++) {
            float ra[8], rb[8];
            *(float4*)(ra)   = *(float4*)&As[kk][tr*8];
            *(float4*)(ra+4) = *(float4*)&As[kk][tr*8+4];
            *(float4*)(rb)   = *(float4*)&Bs[kk][tc*8];
            *(float4*)(rb+4) = *(float4*)&Bs[kk][tc*8+4];
#pragma unroll
            for (int i = 0; i < 8; i++)
#pragma unroll
                for (int j = 0; j < 8; j++)
                    acc[i][j] = fmaf(ra[i], rb[j], acc[i][j]);
        }
        __syncthreads();
    }

#pragma unroll
    for (int i = 0; i < 8; i++) {
        int row = rowBase + tr*8 + i;
        float* Cr = C + (size_t)row * N + colBase + tc*8;
#pragma unroll
        for (int j = 0; j < 8; j += 4) {
            float4 o;
            o.x = acc[i][j+0] + bias[colBase + tc*8 + j+0];
            o.y = acc[i][j+1] + bias[colBase + tc*8 + j+1];
            o.z = acc[i][j+2] + bias[colBase + tc*8 + j+2];
            o.w = acc[i][j+3] + bias[colBase + tc*8 + j+3];
            *(float4*)(Cr + j) = o;
        }
    }
}

// ---------------------------------------------------------------------------
// RoPE (interleaved pairs), applied in-place to q and k.
// ---------------------------------------------------------------------------
__global__ void rope_kernel(float* __restrict__ q, float* __restrict__ k)
{
    int i = blockIdx.x * blockDim.x + threadIdx.x;    // pair index
    const int total = MROWS * NH * (HD/2);
    if (i >= total) return;
    int d   = i & 31;               // 0..31 (pair index within head)
    int row = i >> 9;               // b*SEQ + n   (32*16 = 512 pairs per row)
    int n   = row & (SEQ - 1);

    float inv_freq = powf(10000.0f, -(float)d / 32.0f);
    float ang = (float)n * inv_freq;
    float s, c;
    sincosf(ang, &s, &c);

    int h = (i >> 5) & (NH - 1);
    size_t base = (size_t)row * DM + h * HD + 2*d;

    float a = q[base], b2 = q[base+1];
    q[base]   = a*c - b2*s;
    q[base+1] = a*s + b2*c;
    a = k[base]; b2 = k[base+1];
    k[base]   = a*c - b2*s;
    k[base+1] = a*s + b2*c;
}

// ---------------------------------------------------------------------------
// Flash attention, fp32 SIMT. BQ=32, BK=64, Hd=64, 256 threads.
// Thread (r = tid/8, g = tid%8) owns query row r, output dims [g*8, g*8+8),
// and score columns {g, g+8, ..., g+56} (strided for conflict-free LDS).
// ---------------------------------------------------------------------------
struct AttnSmem {
    float Qs[32][64];
    float Ks[64][68];   // padded: conflict-free score reads
    float Vs[64][64];
    float Ps[32][64];
};

__global__ __launch_bounds__(256) void attn_kernel(
    const float* __restrict__ q, const float* __restrict__ k,
    const float* __restrict__ v, float* __restrict__ o)
{
    extern __shared__ char smem_raw[];
    AttnSmem* sm = (AttnSmem*)smem_raw;

    const int tid = threadIdx.x;
    const int r = tid >> 3;     // 0..31
    const int g = tid & 7;      // 0..7
    const int qt = blockIdx.x, h = blockIdx.y, b = blockIdx.z;

    const float* qb = q + ((size_t)(b*SEQ + qt*32)) * DM + h*HD;
    const float* kb = k + (size_t)b * SEQ * DM + h*HD;
    const float* vb = v + (size_t)b * SEQ * DM + h*HD;

#pragma unroll
    for (int t = 0; t < 2; t++) {
        int idx = tid + t * 256;        // 0..511
        int row = idx >> 4;             // 0..31
        int c4  = (idx & 15) << 2;
        *(float4*)&sm->Qs[row][c4] = *(const float4*)(qb + (size_t)row * DM + c4);
    }

    float acc[8] = {0,0,0,0,0,0,0,0};
    float m = -1e30f, l = 0.f;

    for (int kt = 0; kt < SEQ/64; kt++) {
        __syncthreads();   // previous-iter smem reads done
#pragma unroll
        for (int t = 0; t < 4; t++) {
            int idx = tid + t * 256;    // 0..1023
            int row = idx >> 4;         // 0..63
            int c4  = (idx & 15) << 2;
            size_t goff = (size_t)(kt*64 + row) * DM + c4;
            *(float4*)&sm->Ks[row][c4] = *(const float4*)(kb + goff);
            *(float4*)&sm->Vs[row][c4] = *(const float4*)(vb + goff);
        }
        __syncthreads();

        // scores: s[j] = Q[r] . K[g + 8j]
        float s[8] = {0,0,0,0,0,0,0,0};
#pragma unroll
        for (int kd = 0; kd < 64; kd += 4) {
            float4 qv = *(float4*)&sm->Qs[r][kd];
#pragma unroll
            for (int j = 0; j < 8; j++) {
                float4 kv = *(float4*)&sm->Ks[g + 8*j][kd];
                s[j] = fmaf(qv.x, kv.x, s[j]);
                s[j] = fmaf(qv.y, kv.y, s[j]);
                s[j] = fmaf(qv.z, kv.z, s[j]);
                s[j] = fmaf(qv.w, kv.w, s[j]);
            }
        }

        float lm = -1e30f;
#pragma unroll
        for (int j = 0; j < 8; j++) { s[j] *= 0.125f; lm = fmaxf(lm, s[j]); }
#pragma unroll
        for (int off = 4; off; off >>= 1)
            lm = fmaxf(lm, __shfl_xor_sync(0xffffffffu, lm, off));

        float mn = fmaxf(m, lm);
        float sc = __expf(m - mn);
        float ls = 0.f;
#pragma unroll
        for (int j = 0; j < 8; j++) {
            float p = __expf(s[j] - mn);
            sm->Ps[r][g + 8*j] = p;
            ls += p;
        }
#pragma unroll
        for (int off = 4; off; off >>= 1)
            ls += __shfl_xor_sync(0xffffffffu, ls, off);

        m = mn;
        l = l * sc + ls;
#pragma unroll
        for (int j = 0; j < 8; j++) acc[j] *= sc;
        __syncwarp();

        // O[r][g*8 .. g*8+7] += P[r][:] @ V[:][g*8..]
#pragma unroll 8
        for (int kk = 0; kk < 64; kk++) {
            float p = sm->Ps[r][kk];
            float4 v0 = *(float4*)&sm->Vs[kk][g*8];
            float4 v1 = *(float4*)&sm->Vs[kk][g*8+4];
            acc[0] = fmaf(p, v0.x, acc[0]); acc[1] = fmaf(p, v0.y, acc[1]);
            acc[2] = fmaf(p, v0.z, acc[2]); acc[3] = fmaf(p, v0.w, acc[3]);
            acc[4] = fmaf(p, v1.x, acc[4]); acc[5] = fmaf(p, v1.y, acc[5]);
            acc[6] = fmaf(p, v1.z, acc[6]); acc[7] = fmaf(p, v1.w, acc[7]);
        }
    }

    float inv = 1.f / l;
    float* ob = o + ((size_t)(b*SEQ + qt*32 + r)) * DM + h*HD + g*8;
    float4 o0 = { acc[0]*inv, acc[1]*inv, acc[2]*inv, acc[3]*inv };
    float4 o1 = { acc[4]*inv, acc[5]*inv, acc[6]*inv, acc[7]*inv };
    *(float4*)ob       = o0;
    *((float4*)ob + 1) = o1;
}

// ---------------------------------------------------------------------------

extern "C" void kernel_launch(void* const* d_in, const int* in_sizes, int n_in,
                              void* d_out, int out_size)
{
    const float* x  = (const float*)d_in[0];
    const float* wq = (const float*)d_in[1];
    const float* bq = (const float*)d_in[2];
    const float* wk = (const float*)d_in[3];
    const float* bk = (const float*)d_in[4];
    const float* wv = (const float*)d_in[5];
    const float* bv = (const float*)d_in[6];
    const float* wo = (const float*)d_in[7];
    const float* bo = (const float*)d_in[8];
    float* out = (float*)d_out;

    float *q, *k, *v, *att;
    cudaGetSymbolAddress((void**)&q,   g_q);
    cudaGetSymbolAddress((void**)&k,   g_k);
    cudaGetSymbolAddress((void**)&v,   g_v);
    cudaGetSymbolAddress((void**)&att, g_att);

    dim3 gg(DM/128, MROWS/128);
    sgemm_bias<<<gg, 256>>>(x, wq, bq, q, MROWS, DM, DM);
    sgemm_bias<<<gg, 256>>>(x, wk, bk, k, MROWS, DM, DM);
    sgemm_bias<<<gg, 256>>>(x, wv, bv, v, MROWS, DM, DM);

    int pairs = MROWS * NH * (HD/2);
    rope_kernel<<<(pairs + 255) / 256, 256>>>(q, k);

    int smem = (int)sizeof(AttnSmem);   // 50176 B > 48K -> opt in
    cudaFuncSetAttribute(attn_kernel, cudaFuncAttributeMaxDynamicSharedMemorySize, smem);
    attn_kernel<<<dim3(SEQ/32, NH, BATCH), 256, smem>>>(q, k, v, att);

    sgemm_bias<<<gg, 256>>>(att, wo, bo, out, MROWS, DM, DM);
}

// round 2
// speedup vs baseline: 5.7651x; 5.7651x over previous
#include <cuda_runtime.h>
#include <math.h>

#define BATCH 4
#define SEQ   2048
#define DM    1024
#define NH    16
#define HD    64
#define MROWS (BATCH*SEQ)

// Scratch (device-global; no allocation allowed)
__device__ float g_q[MROWS*DM];
__device__ float g_k[MROWS*DM];
__device__ float g_v[MROWS*DM];
__device__ float g_att[MROWS*DM];

// ---------------------------------------------------------------------------
// tf32 helpers
// ---------------------------------------------------------------------------
__device__ __forceinline__ unsigned f2tf(float x) {
    unsigned r;
    asm("cvt.rna.tf32.f32 %0, %1;" : "=r"(r) : "f"(x));
    return r;
}

__device__ __forceinline__ void mma_tf32(float c[4],
    unsigned a0, unsigned a1, unsigned a2, unsigned a3,
    unsigned b0, unsigned b1)
{
    asm volatile(
        "mma.sync.aligned.m16n8k8.row.col.f32.tf32.tf32.f32 "
        "{%0,%1,%2,%3}, {%4,%5,%6,%7}, {%8,%9}, {%0,%1,%2,%3};"
        : "+f"(c[0]), "+f"(c[1]), "+f"(c[2]), "+f"(c[3])
        : "r"(a0), "r"(a1), "r"(a2), "r"(a3), "r"(b0), "r"(b1));
}

// ---------------------------------------------------------------------------
// GEMM: C[M,N] = A[M,K] @ W[N,K]^T + bias[N]   (tf32 tensor cores)
// 128x128 tile, BK=32, 256 threads (8 warps), warp tile 64x32.
// Smem row-major, pad 36 -> conflict-free fragment LDS: bank=(4g+t)%32.
// ---------------------------------------------------------------------------
#define GPAD 36

__global__ __launch_bounds__(256) void sgemm_tc(
    const float* __restrict__ A, const float* __restrict__ W,
    const float* __restrict__ bias, float* __restrict__ C,
    int M, int N, int K)
{
    __shared__ float As[128][GPAD];
    __shared__ float Bs[128][GPAD];

    const int tid = threadIdx.x;
    const int lane = tid & 31, warp = tid >> 5;
    const int g = lane >> 2, t = lane & 3;
    const int wm = (warp & 1) * 64;
    const int wn = (warp >> 1) * 32;
    const int rowBase = blockIdx.y * 128;
    const int colBase = blockIdx.x * 128;
    const float* Ab = A + (size_t)rowBase * K;
    const float* Wb = W + (size_t)colBase * K;

    float c[4][4][4];
#pragma unroll
    for (int mt = 0; mt < 4; mt++)
#pragma unroll
        for (int nt = 0; nt < 4; nt++)
#pragma unroll
            for (int i = 0; i < 4; i++) c[mt][nt][i] = 0.f;

    for (int k0 = 0; k0 < K; k0 += 32) {
#pragma unroll
        for (int it = 0; it < 4; it++) {
            int idx = tid + it * 256;       // 0..1023
            int row = idx >> 3;             // 0..127
            int kg  = (idx & 7) << 2;       // 0,4,..,28
            float4 av = *(const float4*)(Ab + (size_t)row * K + k0 + kg);
            float4 sv;
            sv.x = __uint_as_float(f2tf(av.x));
            sv.y = __uint_as_float(f2tf(av.y));
            sv.z = __uint_as_float(f2tf(av.z));
            sv.w = __uint_as_float(f2tf(av.w));
            *(float4*)&As[row][kg] = sv;
            float4 wv = *(const float4*)(Wb + (size_t)row * K + k0 + kg);
            sv.x = __uint_as_float(f2tf(wv.x));
            sv.y = __uint_as_float(f2tf(wv.y));
            sv.z = __uint_as_float(f2tf(wv.z));
            sv.w = __uint_as_float(f2tf(wv.w));
            *(float4*)&Bs[row][kg] = sv;
        }
        __syncthreads();

#pragma unroll
        for (int ks = 0; ks < 4; ks++) {
            int kk = ks * 8;
            unsigned a[4][4], b[4][2];
#pragma unroll
            for (int mt = 0; mt < 4; mt++) {
                int r0 = wm + mt * 16;
                a[mt][0] = __float_as_uint(As[r0 + g    ][kk + t    ]);
                a[mt][1] = __float_as_uint(As[r0 + g + 8][kk + t    ]);
                a[mt][2] = __float_as_uint(As[r0 + g    ][kk + t + 4]);
                a[mt][3] = __float_as_uint(As[r0 + g + 8][kk + t + 4]);
            }
#pragma unroll
            for (int nt = 0; nt < 4; nt++) {
                int n0 = wn + nt * 8;
                b[nt][0] = __float_as_uint(Bs[n0 + g][kk + t    ]);
                b[nt][1] = __float_as_uint(Bs[n0 + g][kk + t + 4]);
            }
#pragma unroll
            for (int mt = 0; mt < 4; mt++)
#pragma unroll
                for (int nt = 0; nt < 4; nt++)
                    mma_tf32(c[mt][nt], a[mt][0], a[mt][1], a[mt][2], a[mt][3],
                             b[nt][0], b[nt][1]);
        }
        __syncthreads();
    }

#pragma unroll
    for (int mt = 0; mt < 4; mt++) {
        int r = rowBase + wm + mt * 16;
#pragma unroll
        for (int nt = 0; nt < 4; nt++) {
            int col = colBase + wn + nt * 8 + 2 * t;
            float b0 = bias[col], b1 = bias[col + 1];
            float2 v0 = { c[mt][nt][0] + b0, c[mt][nt][1] + b1 };
            *(float2*)(C + (size_t)(r + g) * N + col) = v0;
            float2 v1 = { c[mt][nt][2] + b0, c[mt][nt][3] + b1 };
            *(float2*)(C + (size_t)(r + g + 8) * N + col) = v1;
        }
    }
}

// ---------------------------------------------------------------------------
// RoPE (interleaved pairs), applied in-place to q and k.
// ---------------------------------------------------------------------------
__global__ void rope_kernel(float* __restrict__ q, float* __restrict__ k)
{
    int i = blockIdx.x * blockDim.x + threadIdx.x;    // pair index
    const int total = MROWS * NH * (HD/2);
    if (i >= total) return;
    int d   = i & 31;               // pair index within head
    int row = i >> 9;               // b*SEQ + n
    int n   = row & (SEQ - 1);

    float inv_freq = powf(10000.0f, -(float)d / 32.0f);
    float ang = (float)n * inv_freq;
    float s, c;
    sincosf(ang, &s, &c);

    int h = (i >> 5) & (NH - 1);
    size_t base = (size_t)row * DM + h * HD + 2 * d;

    float a = q[base], b2 = q[base + 1];
    q[base]     = a * c - b2 * s;
    q[base + 1] = a * s + b2 * c;
    a = k[base]; b2 = k[base + 1];
    k[base]     = a * c - b2 * s;
    k[base + 1] = a * s + b2 * c;
}

// ---------------------------------------------------------------------------
// Flash attention with tf32 tensor cores.
// BQ=64, BK=64, Hd=64, 128 threads (4 warps). Warp w owns rows w*16..w*16+15.
// S = (Q*0.125) @ K^T via m16n8k8; online softmax in frags; P -> smem (tf32);
// O += P @ V via m16n8k8.
// ---------------------------------------------------------------------------
#define APAD 68

struct AttnSmem {
    float Qs[64][APAD];
    float Ks[64][APAD];
    float Vs[64][APAD];
    float Ps[64][APAD];
};

__global__ __launch_bounds__(128) void attn_tc(
    const float* __restrict__ q, const float* __restrict__ k,
    const float* __restrict__ v, float* __restrict__ o)
{
    extern __shared__ char sraw[];
    AttnSmem* sm = (AttnSmem*)sraw;

    const int tid = threadIdx.x;
    const int lane = tid & 31, warp = tid >> 5;
    const int g = lane >> 2, t = lane & 3;
    const int r0 = warp * 16;
    const int qt = blockIdx.x, h = blockIdx.y, b = blockIdx.z;

    const float* qb = q + ((size_t)(b * SEQ + qt * 64)) * DM + h * HD;
    const float* kb = k + (size_t)b * SEQ * DM + h * HD;
    const float* vb = v + (size_t)b * SEQ * DM + h * HD;

    // Load Q tile (pre-scaled by 1/sqrt(64)=0.125, tf32)
#pragma unroll
    for (int it = 0; it < 8; it++) {
        int idx = tid + it * 128;      // 0..1023
        int row = idx >> 4;            // 0..63
        int c4  = (idx & 15) << 2;
        float4 av = *(const float4*)(qb + (size_t)row * DM + c4);
        float4 sv;
        sv.x = __uint_as_float(f2tf(av.x * 0.125f));
        sv.y = __uint_as_float(f2tf(av.y * 0.125f));
        sv.z = __uint_as_float(f2tf(av.z * 0.125f));
        sv.w = __uint_as_float(f2tf(av.w * 0.125f));
        *(float4*)&sm->Qs[row][c4] = sv;
    }

    float m0 = -1e30f, m1 = -1e30f, l0 = 0.f, l1 = 0.f;
    float oacc[8][4];
#pragma unroll
    for (int nt = 0; nt < 8; nt++)
#pragma unroll
        for (int i = 0; i < 4; i++) oacc[nt][i] = 0.f;

    for (int kt = 0; kt < SEQ / 64; kt++) {
        __syncthreads();
#pragma unroll
        for (int it = 0; it < 8; it++) {
            int idx = tid + it * 128;
            int row = idx >> 4;
            int c4  = (idx & 15) << 2;
            size_t off = (size_t)(kt * 64 + row) * DM + c4;
            float4 kv = *(const float4*)(kb + off);
            float4 sv;
            sv.x = __uint_as_float(f2tf(kv.x));
            sv.y = __uint_as_float(f2tf(kv.y));
            sv.z = __uint_as_float(f2tf(kv.z));
            sv.w = __uint_as_float(f2tf(kv.w));
            *(float4*)&sm->Ks[row][c4] = sv;
            float4 vv = *(const float4*)(vb + off);
            sv.x = __uint_as_float(f2tf(vv.x));
            sv.y = __uint_as_float(f2tf(vv.y));
            sv.z = __uint_as_float(f2tf(vv.z));
            sv.w = __uint_as_float(f2tf(vv.w));
            *(float4*)&sm->Vs[row][c4] = sv;
        }
        __syncthreads();

        // S = Q @ K^T
        float s[8][4];
#pragma unroll
        for (int nt = 0; nt < 8; nt++)
#pragma unroll
            for (int i = 0; i < 4; i++) s[nt][i] = 0.f;

#pragma unroll
        for (int ks = 0; ks < 8; ks++) {
            int kk = ks * 8;
            unsigned a0 = __float_as_uint(sm->Qs[r0 + g    ][kk + t    ]);
            unsigned a1 = __float_as_uint(sm->Qs[r0 + g + 8][kk + t    ]);
            unsigned a2 = __float_as_uint(sm->Qs[r0 + g    ][kk + t + 4]);
            unsigned a3 = __float_as_uint(sm->Qs[r0 + g + 8][kk + t + 4]);
#pragma unroll
            for (int nt = 0; nt < 8; nt++) {
                unsigned b0 = __float_as_uint(sm->Ks[nt * 8 + g][kk + t    ]);
                unsigned b1 = __float_as_uint(sm->Ks[nt * 8 + g][kk + t + 4]);
                mma_tf32(s[nt], a0, a1, a2, a3, b0, b1);
            }
        }

        // Online softmax (rows g and g+8 of this warp's 16)
        float lm0 = -1e30f, lm1 = -1e30f;
#pragma unroll
        for (int nt = 0; nt < 8; nt++) {
            lm0 = fmaxf(lm0, fmaxf(s[nt][0], s[nt][1]));
            lm1 = fmaxf(lm1, fmaxf(s[nt][2], s[nt][3]));
        }
#pragma unroll
        for (int off = 1; off <= 2; off <<= 1) {
            lm0 = fmaxf(lm0, __shfl_xor_sync(0xffffffffu, lm0, off));
            lm1 = fmaxf(lm1, __shfl_xor_sync(0xffffffffu, lm1, off));
        }
        float mn0 = fmaxf(m0, lm0), mn1 = fmaxf(m1, lm1);
        float sc0 = __expf(m0 - mn0), sc1 = __expf(m1 - mn1);
        m0 = mn0; m1 = mn1;

        float ll0 = 0.f, ll1 = 0.f;
#pragma unroll
        for (int nt = 0; nt < 8; nt++) {
            float p0 = __expf(s[nt][0] - mn0);
            float p1 = __expf(s[nt][1] - mn0);
            float p2 = __expf(s[nt][2] - mn1);
            float p3 = __expf(s[nt][3] - mn1);
            ll0 += p0 + p1;
            ll1 += p2 + p3;
            float2 w0 = { __uint_as_float(f2tf(p0)), __uint_as_float(f2tf(p1)) };
            *(float2*)&sm->Ps[r0 + g][nt * 8 + 2 * t] = w0;
            float2 w1 = { __uint_as_float(f2tf(p2)), __uint_as_float(f2tf(p3)) };
            *(float2*)&sm->Ps[r0 + g + 8][nt * 8 + 2 * t] = w1;
            oacc[nt][0] *= sc0; oacc[nt][1] *= sc0;
            oacc[nt][2] *= sc1; oacc[nt][3] *= sc1;
        }
#pragma unroll
        for (int off = 1; off <= 2; off <<= 1) {
            ll0 += __shfl_xor_sync(0xffffffffu, ll0, off);
            ll1 += __shfl_xor_sync(0xffffffffu, ll1, off);
        }
        l0 = l0 * sc0 + ll0;
        l1 = l1 * sc1 + ll1;
        __syncwarp();

        // O += P @ V
#pragma unroll
        for (int ks = 0; ks < 8; ks++) {
            int kk = ks * 8;
            unsigned a0 = __float_as_uint(sm->Ps[r0 + g    ][kk + t    ]);
            unsigned a1 = __float_as_uint(sm->Ps[r0 + g + 8][kk + t    ]);
            unsigned a2 = __float_as_uint(sm->Ps[r0 + g    ][kk + t + 4]);
            unsigned a3 = __float_as_uint(sm->Ps[r0 + g + 8][kk + t + 4]);
#pragma unroll
            for (int nt = 0; nt < 8; nt++) {
                unsigned b0 = __float_as_uint(sm->Vs[kk + t    ][nt * 8 + g]);
                unsigned b1 = __float_as_uint(sm->Vs[kk + t + 4][nt * 8 + g]);
                mma_tf32(oacc[nt], a0, a1, a2, a3, b0, b1);
            }
        }
    }

    float inv0 = 1.f / l0, inv1 = 1.f / l1;
    size_t rowg = (size_t)(b * SEQ + qt * 64 + r0 + g);
    float* ob = o + rowg * DM + h * HD;
#pragma unroll
    for (int nt = 0; nt < 8; nt++) {
        float2 w0 = { oacc[nt][0] * inv0, oacc[nt][1] * inv0 };
        *(float2*)(ob + nt * 8 + 2 * t) = w0;
        float2 w1 = { oacc[nt][2] * inv1, oacc[nt][3] * inv1 };
        *(float2*)(ob + (size_t)8 * DM + nt * 8 + 2 * t) = w1;
    }
}

// ---------------------------------------------------------------------------

extern "C" void kernel_launch(void* const* d_in, const int* in_sizes, int n_in,
                              void* d_out, int out_size)
{
    const float* x  = (const float*)d_in[0];
    const float* wq = (const float*)d_in[1];
    const float* bq = (const float*)d_in[2];
    const float* wk = (const float*)d_in[3];
    const float* bk = (const float*)d_in[4];
    const float* wv = (const float*)d_in[5];
    const float* bv = (const float*)d_in[6];
    const float* wo = (const float*)d_in[7];
    const float* bo = (const float*)d_in[8];
    float* out = (float*)d_out;

    float *q, *k, *v, *att;
    cudaGetSymbolAddress((void**)&q,   g_q);
    cudaGetSymbolAddress((void**)&k,   g_k);
    cudaGetSymbolAddress((void**)&v,   g_v);
    cudaGetSymbolAddress((void**)&att, g_att);

    dim3 gg(DM / 128, MROWS / 128);
    sgemm_tc<<<gg, 256>>>(x, wq, bq, q, MROWS, DM, DM);
    sgemm_tc<<<gg, 256>>>(x, wk, bk, k, MROWS, DM, DM);
    sgemm_tc<<<gg, 256>>>(x, wv, bv, v, MROWS, DM, DM);

    int pairs = MROWS * NH * (HD / 2);
    rope_kernel<<<(pairs + 255) / 256, 256>>>(q, k);

    int smem = (int)sizeof(AttnSmem);   // 69,632 B -> opt in
    cudaFuncSetAttribute(attn_tc, cudaFuncAttributeMaxDynamicSharedMemorySize, smem);
    attn_tc<<<dim3(SEQ / 64, NH, BATCH), 128, smem>>>(q, k, v, att);

    sgemm_tc<<<gg, 256>>>(att, wo, bo, out, MROWS, DM, DM);
}

// round 5
// speedup vs baseline: 6.4685x; 1.1220x over previous
#include <cuda_runtime.h>
#include <math.h>
#include <stdint.h>

#define BATCH 4
#define SEQ   2048
#define DM    1024
#define NH    16
#define HD    64
#define MROWS (BATCH*SEQ)

// Scratch (device-global; no allocation allowed)
__device__ float g_q[MROWS*DM];
__device__ float g_k[MROWS*DM];
__device__ float g_v[MROWS*DM];
__device__ float g_att[MROWS*DM];
__device__ float g_xr[MROWS*DM];      // RNA-rounded x
__device__ float g_wr[4][DM*DM];      // RNA-rounded wq,wk,wv,wo

// ---------------------------------------------------------------------------
// helpers
// ---------------------------------------------------------------------------
__device__ __forceinline__ uint32_t su32(const void* p) {
    return (uint32_t)__cvta_generic_to_shared(p);
}
__device__ __forceinline__ void cpa16(uint32_t dst, const void* src) {
    asm volatile("cp.async.cg.shared.global [%0], [%1], 16;" :: "r"(dst), "l"(src));
}
#define CP_COMMIT asm volatile("cp.async.commit_group;" ::: "memory")
#define CP_WAIT1  asm volatile("cp.async.wait_group 1;" ::: "memory")
#define CP_WAIT0  asm volatile("cp.async.wait_group 0;" ::: "memory")

__device__ __forceinline__ float f2tf(float x) {
    unsigned r;
    asm("cvt.rna.tf32.f32 %0, %1;" : "=r"(r) : "f"(x));
    return __uint_as_float(r);
}

__device__ __forceinline__ void mma_tf32(float c[4],
    unsigned a0, unsigned a1, unsigned a2, unsigned a3,
    unsigned b0, unsigned b1)
{
    asm volatile(
        "mma.sync.aligned.m16n8k8.row.col.f32.tf32.tf32.f32 "
        "{%0,%1,%2,%3}, {%4,%5,%6,%7}, {%8,%9}, {%0,%1,%2,%3};"
        : "+f"(c[0]), "+f"(c[1]), "+f"(c[2]), "+f"(c[3])
        : "r"(a0), "r"(a1), "r"(a2), "r"(a3), "r"(b0), "r"(b1));
}

// ---------------------------------------------------------------------------
// Pre-round: dst = cvt.rna.tf32(src), vectorized
// ---------------------------------------------------------------------------
__global__ void round_tf32(const float* __restrict__ src, float* __restrict__ dst, int n4)
{
    int i = blockIdx.x * blockDim.x + threadIdx.x;
    if (i >= n4) return;
    float4 v = ((const float4*)src)[i];
    v.x = f2tf(v.x); v.y = f2tf(v.y); v.z = f2tf(v.z); v.w = f2tf(v.w);
    ((float4*)dst)[i] = v;
}

// ---------------------------------------------------------------------------
// GEMM: C[M,N] = A[M,K] @ W[N,K]^T + bias[N]   (tf32, cp.async 2-stage)
// 128x128 tile, BK=32, 256 threads (8 warps), warp tile 64x32.
// Inputs must be pre-rounded to tf32 (RNA). Optional fused RoPE,
// optional RNA rounding of the output (when it feeds another MMA).
// ---------------------------------------------------------------------------
#define GPAD 36
struct GSmem { float As[2][128][GPAD]; float Bs[2][128][GPAD]; };

__global__ __launch_bounds__(256) void sgemm_tc(
    const float* __restrict__ A, const float* __restrict__ W,
    const float* __restrict__ bias, float* __restrict__ C,
    int do_rope, int do_round)
{
    extern __shared__ char sraw[];
    GSmem* sm = (GSmem*)sraw;

    const int tid = threadIdx.x;
    const int lane = tid & 31, warp = tid >> 5;
    const int g = lane >> 2, t = lane & 3;
    const int wm = (warp & 1) * 64;
    const int wn = (warp >> 1) * 32;
    const int rowBase = blockIdx.y * 128;
    const int colBase = blockIdx.x * 128;
    const float* Ab = A + (size_t)rowBase * DM;
    const float* Wb = W + (size_t)colBase * DM;

    float c[4][4][4];
#pragma unroll
    for (int mt = 0; mt < 4; mt++)
#pragma unroll
        for (int nt = 0; nt < 4; nt++)
#pragma unroll
            for (int i = 0; i < 4; i++) c[mt][nt][i] = 0.f;

    auto issue = [&](int kb, int st) {
#pragma unroll
        for (int it = 0; it < 4; it++) {
            int idx = tid + it * 256;       // 0..1023
            int row = idx >> 3;             // 0..127
            int kg  = (idx & 7) << 2;       // 0,4,..,28
            cpa16(su32(&sm->As[st][row][kg]), Ab + (size_t)row * DM + kb * 32 + kg);
            cpa16(su32(&sm->Bs[st][row][kg]), Wb + (size_t)row * DM + kb * 32 + kg);
        }
        CP_COMMIT;
    };

    issue(0, 0);

    for (int kb = 0; kb < DM / 32; kb++) {
        int st = kb & 1;
        if (kb + 1 < DM / 32) { issue(kb + 1, st ^ 1); CP_WAIT1; }
        else                  { CP_WAIT0; }
        __syncthreads();

#pragma unroll
        for (int ks = 0; ks < 4; ks++) {
            int kk = ks * 8;
            unsigned a[4][4], b[4][2];
#pragma unroll
            for (int mt = 0; mt < 4; mt++) {
                int r0 = wm + mt * 16;
                a[mt][0] = __float_as_uint(sm->As[st][r0 + g    ][kk + t    ]);
                a[mt][1] = __float_as_uint(sm->As[st][r0 + g + 8][kk + t    ]);
                a[mt][2] = __float_as_uint(sm->As[st][r0 + g    ][kk + t + 4]);
                a[mt][3] = __float_as_uint(sm->As[st][r0 + g + 8][kk + t + 4]);
            }
#pragma unroll
            for (int nt = 0; nt < 4; nt++) {
                int n0 = wn + nt * 8;
                b[nt][0] = __float_as_uint(sm->Bs[st][n0 + g][kk + t    ]);
                b[nt][1] = __float_as_uint(sm->Bs[st][n0 + g][kk + t + 4]);
            }
#pragma unroll
            for (int mt = 0; mt < 4; mt++)
#pragma unroll
                for (int nt = 0; nt < 4; nt++)
                    mma_tf32(c[mt][nt], a[mt][0], a[mt][1], a[mt][2], a[mt][3],
                             b[nt][0], b[nt][1]);
        }
        __syncthreads();
    }

#pragma unroll
    for (int mt = 0; mt < 4; mt++) {
        int row0 = rowBase + wm + mt * 16 + g;
#pragma unroll
        for (int nt = 0; nt < 4; nt++) {
            int col = colBase + wn + nt * 8 + 2 * t;      // even
            float b0 = bias[col], b1 = bias[col + 1];
            float y0 = c[mt][nt][0] + b0, y1 = c[mt][nt][1] + b1;
            float z0 = c[mt][nt][2] + b0, z1 = c[mt][nt][3] + b1;
            if (do_rope) {
                int d = (col & 63) >> 1;
                float invf = powf(10000.0f, -(float)d / 32.0f);
                int n0 = row0 & (SEQ - 1);
                float s0, c0;
                sincosf((float)n0 * invf, &s0, &c0);
                float u0 = y0 * c0 - y1 * s0;
                float u1 = y0 * s0 + y1 * c0;
                y0 = u0; y1 = u1;
                float s1, c1;
                sincosf((float)(n0 + 8) * invf, &s1, &c1);
                float w0 = z0 * c1 - z1 * s1;
                float w1 = z0 * s1 + z1 * c1;
                z0 = w0; z1 = w1;
            }
            if (do_round) {
                y0 = f2tf(y0); y1 = f2tf(y1);
                z0 = f2tf(z0); z1 = f2tf(z1);
            }
            float2 v0 = { y0, y1 };
            *(float2*)(C + (size_t)row0 * DM + col) = v0;
            float2 v1 = { z0, z1 };
            *(float2*)(C + (size_t)(row0 + 8) * DM + col) = v1;
        }
    }
}

// ---------------------------------------------------------------------------
// Flash attention, tf32 tensor cores, cp.async 2-stage K/V pipeline.
// BQ=128, BK=64, Hd=64, 256 threads (8 warps). Warp w rows w*16..w*16+15.
// q/k/v are pre-rounded tf32. P rounded in-register; output rounded (feeds
// the final GEMM).
// ---------------------------------------------------------------------------
#define APAD 68
struct ASmem {
    float Qs[128][APAD];
    float Ps[128][APAD];
    float Ks[2][64][APAD];
    float Vs[2][64][APAD];
};

__global__ __launch_bounds__(256) void attn_tc(
    const float* __restrict__ q, const float* __restrict__ k,
    const float* __restrict__ v, float* __restrict__ o)
{
    extern __shared__ char sraw[];
    ASmem* sm = (ASmem*)sraw;

    const int tid = threadIdx.x;
    const int lane = tid & 31, warp = tid >> 5;
    const int g = lane >> 2, t = lane & 3;
    const int r0 = warp * 16;
    const int qt = blockIdx.x, h = blockIdx.y, b = blockIdx.z;

    const float* qb = q + ((size_t)(b * SEQ + qt * 128)) * DM + h * HD;
    const float* kb = k + (size_t)b * SEQ * DM + h * HD;
    const float* vb = v + (size_t)b * SEQ * DM + h * HD;

    // Q tile: 128x64 via cp.async (own group)
#pragma unroll
    for (int it = 0; it < 8; it++) {
        int idx = tid + it * 256;      // 0..2047
        int row = idx >> 4;            // 0..127
        int c4  = (idx & 15) << 2;
        cpa16(su32(&sm->Qs[row][c4]), qb + (size_t)row * DM + c4);
    }
    CP_COMMIT;

    auto issueKV = [&](int kt, int st) {
#pragma unroll
        for (int it = 0; it < 4; it++) {
            int idx = tid + it * 256;   // 0..1023
            int row = idx >> 4;         // 0..63
            int c4  = (idx & 15) << 2;
            size_t off = (size_t)(kt * 64 + row) * DM + c4;
            cpa16(su32(&sm->Ks[st][row][c4]), kb + off);
            cpa16(su32(&sm->Vs[st][row][c4]), vb + off);
        }
        CP_COMMIT;
    };

    issueKV(0, 0);

    float m0 = -1e30f, m1 = -1e30f, l0 = 0.f, l1 = 0.f;
    float oacc[8][4];
#pragma unroll
    for (int nt = 0; nt < 8; nt++)
#pragma unroll
        for (int i = 0; i < 4; i++) oacc[nt][i] = 0.f;

    for (int kt = 0; kt < SEQ / 64; kt++) {
        int st = kt & 1;
        if (kt + 1 < SEQ / 64) { issueKV(kt + 1, st ^ 1); CP_WAIT1; }
        else                   { CP_WAIT0; }
        __syncthreads();

        // S = Q @ K^T   (1/sqrt(d) applied post-MMA; exact: 0.125 = 2^-3)
        float s[8][4];
#pragma unroll
        for (int nt = 0; nt < 8; nt++)
#pragma unroll
            for (int i = 0; i < 4; i++) s[nt][i] = 0.f;

#pragma unroll
        for (int ks = 0; ks < 8; ks++) {
            int kk = ks * 8;
            unsigned a0 = __float_as_uint(sm->Qs[r0 + g    ][kk + t    ]);
            unsigned a1 = __float_as_uint(sm->Qs[r0 + g + 8][kk + t    ]);
            unsigned a2 = __float_as_uint(sm->Qs[r0 + g    ][kk + t + 4]);
            unsigned a3 = __float_as_uint(sm->Qs[r0 + g + 8][kk + t + 4]);
#pragma unroll
            for (int nt = 0; nt < 8; nt++) {
                unsigned b0 = __float_as_uint(sm->Ks[st][nt * 8 + g][kk + t    ]);
                unsigned b1 = __float_as_uint(sm->Ks[st][nt * 8 + g][kk + t + 4]);
                mma_tf32(s[nt], a0, a1, a2, a3, b0, b1);
            }
        }

        // Online softmax (rows g, g+8 of this warp's 16)
        float lm0 = -1e30f, lm1 = -1e30f;
#pragma unroll
        for (int nt = 0; nt < 8; nt++) {
#pragma unroll
            for (int i = 0; i < 4; i++) s[nt][i] *= 0.125f;
            lm0 = fmaxf(lm0, fmaxf(s[nt][0], s[nt][1]));
            lm1 = fmaxf(lm1, fmaxf(s[nt][2], s[nt][3]));
        }
#pragma unroll
        for (int off = 1; off <= 2; off <<= 1) {
            lm0 = fmaxf(lm0, __shfl_xor_sync(0xffffffffu, lm0, off));
            lm1 = fmaxf(lm1, __shfl_xor_sync(0xffffffffu, lm1, off));
        }
        float mn0 = fmaxf(m0, lm0), mn1 = fmaxf(m1, lm1);
        float sc0 = __expf(m0 - mn0), sc1 = __expf(m1 - mn1);
        m0 = mn0; m1 = mn1;

        float ll0 = 0.f, ll1 = 0.f;
#pragma unroll
        for (int nt = 0; nt < 8; nt++) {
            float p0 = __expf(s[nt][0] - mn0);
            float p1 = __expf(s[nt][1] - mn0);
            float p2 = __expf(s[nt][2] - mn1);
            float p3 = __expf(s[nt][3] - mn1);
            ll0 += p0 + p1;
            ll1 += p2 + p3;
            float2 w0 = { f2tf(p0), f2tf(p1) };
            *(float2*)&sm->Ps[r0 + g][nt * 8 + 2 * t] = w0;
            float2 w1 = { f2tf(p2), f2tf(p3) };
            *(float2*)&sm->Ps[r0 + g + 8][nt * 8 + 2 * t] = w1;
            oacc[nt][0] *= sc0; oacc[nt][1] *= sc0;
            oacc[nt][2] *= sc1; oacc[nt][3] *= sc1;
        }
#pragma unroll
        for (int off = 1; off <= 2; off <<= 1) {
            ll0 += __shfl_xor_sync(0xffffffffu, ll0, off);
            ll1 += __shfl_xor_sync(0xffffffffu, ll1, off);
        }
        l0 = l0 * sc0 + ll0;
        l1 = l1 * sc1 + ll1;
        __syncwarp();

        // O += P @ V
#pragma unroll
        for (int ks = 0; ks < 8; ks++) {
            int kk = ks * 8;
            unsigned a0 = __float_as_uint(sm->Ps[r0 + g    ][kk + t    ]);
            unsigned a1 = __float_as_uint(sm->Ps[r0 + g + 8][kk + t    ]);
            unsigned a2 = __float_as_uint(sm->Ps[r0 + g    ][kk + t + 4]);
            unsigned a3 = __float_as_uint(sm->Ps[r0 + g + 8][kk + t + 4]);
#pragma unroll
            for (int nt = 0; nt < 8; nt++) {
                unsigned b0 = __float_as_uint(sm->Vs[st][kk + t    ][nt * 8 + g]);
                unsigned b1 = __float_as_uint(sm->Vs[st][kk + t + 4][nt * 8 + g]);
                mma_tf32(oacc[nt], a0, a1, a2, a3, b0, b1);
            }
        }
        __syncthreads();   // stage reuse guard
    }

    float inv0 = 1.f / l0, inv1 = 1.f / l1;
    size_t rowg = (size_t)(b * SEQ + qt * 128 + r0 + g);
    float* ob = o + rowg * DM + h * HD;
#pragma unroll
    for (int nt = 0; nt < 8; nt++) {
        float2 w0 = { f2tf(oacc[nt][0] * inv0), f2tf(oacc[nt][1] * inv0) };
        *(float2*)(ob + nt * 8 + 2 * t) = w0;
        float2 w1 = { f2tf(oacc[nt][2] * inv1), f2tf(oacc[nt][3] * inv1) };
        *(float2*)(ob + (size_t)8 * DM + nt * 8 + 2 * t) = w1;
    }
}

// ---------------------------------------------------------------------------

extern "C" void kernel_launch(void* const* d_in, const int* in_sizes, int n_in,
                              void* d_out, int out_size)
{
    const float* x  = (const float*)d_in[0];
    const float* wq = (const float*)d_in[1];
    const float* bq = (const float*)d_in[2];
    const float* wk = (const float*)d_in[3];
    const float* bk = (const float*)d_in[4];
    const float* wv = (const float*)d_in[5];
    const float* bv = (const float*)d_in[6];
    const float* wo = (const float*)d_in[7];
    const float* bo = (const float*)d_in[8];
    float* out = (float*)d_out;

    float *q, *k, *v, *att, *xr, *wr;
    cudaGetSymbolAddress((void**)&q,   g_q);
    cudaGetSymbolAddress((void**)&k,   g_k);
    cudaGetSymbolAddress((void**)&v,   g_v);
    cudaGetSymbolAddress((void**)&att, g_att);
    cudaGetSymbolAddress((void**)&xr,  g_xr);
    cudaGetSymbolAddress((void**)&wr,  g_wr);
    float* wqr = wr;
    float* wkr = wr + (size_t)DM * DM;
    float* wvr = wr + (size_t)2 * DM * DM;
    float* wor = wr + (size_t)3 * DM * DM;

    // Pre-round inputs to tf32 (RNA)
    {
        int n4x = MROWS * DM / 4, n4w = DM * DM / 4;
        round_tf32<<<(n4x + 255) / 256, 256>>>(x, xr, n4x);
        round_tf32<<<(n4w + 255) / 256, 256>>>(wq, wqr, n4w);
        round_tf32<<<(n4w + 255) / 256, 256>>>(wk, wkr, n4w);
        round_tf32<<<(n4w + 255) / 256, 256>>>(wv, wvr, n4w);
        round_tf32<<<(n4w + 255) / 256, 256>>>(wo, wor, n4w);
    }

    int gsm = (int)sizeof(GSmem);    // 73,728 B
    cudaFuncSetAttribute(sgemm_tc, cudaFuncAttributeMaxDynamicSharedMemorySize, gsm);
    int asm_ = (int)sizeof(ASmem);   // 139,264 B
    cudaFuncSetAttribute(attn_tc, cudaFuncAttributeMaxDynamicSharedMemorySize, asm_);

    dim3 gg(DM / 128, MROWS / 128);
    sgemm_tc<<<gg, 256, gsm>>>(xr, wqr, bq, q, 1, 1);   // fused RoPE, rounded out
    sgemm_tc<<<gg, 256, gsm>>>(xr, wkr, bk, k, 1, 1);   // fused RoPE, rounded out
    sgemm_tc<<<gg, 256, gsm>>>(xr, wvr, bv, v, 0, 1);

    attn_tc<<<dim3(SEQ / 128, NH, BATCH), 256, asm_>>>(q, k, v, att);

    sgemm_tc<<<gg, 256, gsm>>>(att, wor, bo, out, 0, 0);
}

// round 6
// speedup vs baseline: 12.3736x; 1.9129x over previous
#include <cuda_runtime.h>
#include <cuda_fp16.h>
#include <math.h>
#include <stdint.h>

#define BATCH 4
#define SEQ   2048
#define DM    1024
#define NH    16
#define HD    64
#define MROWS (BATCH*SEQ)

// Scratch (device-global; no allocation allowed)
__device__ __half g_xh[MROWS*DM];
__device__ __half g_wh[4][DM*DM];
__device__ __half g_q[MROWS*DM];
__device__ __half g_k[MROWS*DM];
__device__ __half g_v[MROWS*DM];
__device__ __half g_att[MROWS*DM];

// ---------------------------------------------------------------------------
// helpers
// ---------------------------------------------------------------------------
__device__ __forceinline__ uint32_t su32(const void* p) {
    return (uint32_t)__cvta_generic_to_shared(p);
}
__device__ __forceinline__ void cpa16(uint32_t dst, const void* src) {
    asm volatile("cp.async.cg.shared.global [%0], [%1], 16;" :: "r"(dst), "l"(src));
}
#define CP_COMMIT asm volatile("cp.async.commit_group;" ::: "memory")
#define CP_WAIT1  asm volatile("cp.async.wait_group 1;" ::: "memory")
#define CP_WAIT0  asm volatile("cp.async.wait_group 0;" ::: "memory")

__device__ __forceinline__ void mma_f16(float c[4],
    unsigned a0, unsigned a1, unsigned a2, unsigned a3,
    unsigned b0, unsigned b1)
{
    asm volatile(
        "mma.sync.aligned.m16n8k16.row.col.f32.f16.f16.f32 "
        "{%0,%1,%2,%3}, {%4,%5,%6,%7}, {%8,%9}, {%0,%1,%2,%3};"
        : "+f"(c[0]), "+f"(c[1]), "+f"(c[2]), "+f"(c[3])
        : "r"(a0), "r"(a1), "r"(a2), "r"(a3), "r"(b0), "r"(b1));
}

__device__ __forceinline__ unsigned ldu(const __half* p) {
    return *(const unsigned*)p;
}
__device__ __forceinline__ unsigned packh(__half lo, __half hi) {
    __half2 h = __halves2half2(lo, hi);
    return *(unsigned*)&h;
}

// ---------------------------------------------------------------------------
// fp32 -> fp16 convert (RN), 8 elements/thread
// ---------------------------------------------------------------------------
__global__ void f2h(const float* __restrict__ src, __half* __restrict__ dst, int n8)
{
    int i = blockIdx.x * blockDim.x + threadIdx.x;
    if (i >= n8) return;
    float4 v0 = ((const float4*)src)[2*i];
    float4 v1 = ((const float4*)src)[2*i + 1];
    __half2 h0 = __floats2half2_rn(v0.x, v0.y);
    __half2 h1 = __floats2half2_rn(v0.z, v0.w);
    __half2 h2 = __floats2half2_rn(v1.x, v1.y);
    __half2 h3 = __floats2half2_rn(v1.z, v1.w);
    uint4 o = { *(unsigned*)&h0, *(unsigned*)&h1, *(unsigned*)&h2, *(unsigned*)&h3 };
    ((uint4*)dst)[i] = o;
}

// ---------------------------------------------------------------------------
// GEMM: C[M,N] = A[M,K] @ W[N,K]^T + bias[N]   (fp16 MMA, f32 accum)
// 128x128 tile, BK=64, 256 threads (8 warps), warp tile 64x32, cp.async 2-stage.
// Row pad: 64+8 halves (36 words) -> all fragment LDS conflict-free.
// ---------------------------------------------------------------------------
#define GROW 72
struct GSmem { __half As[2][128][GROW]; __half Bs[2][128][GROW]; };

__global__ __launch_bounds__(256) void hgemm(
    const __half* __restrict__ A, const __half* __restrict__ W,
    const float* __restrict__ bias, __half* __restrict__ Ch,
    float* __restrict__ Cf, int do_rope)
{
    extern __shared__ char sraw[];
    GSmem* sm = (GSmem*)sraw;

    const int tid = threadIdx.x;
    const int lane = tid & 31, warp = tid >> 5;
    const int g = lane >> 2, t = lane & 3;
    const int wm = (warp & 1) * 64;
    const int wn = (warp >> 1) * 32;
    const int rowBase = blockIdx.y * 128;
    const int colBase = blockIdx.x * 128;
    const __half* Ab = A + (size_t)rowBase * DM;
    const __half* Wb = W + (size_t)colBase * DM;

    float c[4][4][4];
#pragma unroll
    for (int mt = 0; mt < 4; mt++)
#pragma unroll
        for (int nt = 0; nt < 4; nt++)
#pragma unroll
            for (int i = 0; i < 4; i++) c[mt][nt][i] = 0.f;

    auto issue = [&](int kb, int st) {
#pragma unroll
        for (int it = 0; it < 4; it++) {
            int idx = tid + it * 256;       // 0..1023
            int row = idx >> 3;             // 0..127
            int sg  = (idx & 7) << 3;       // 0,8,..,56 halves (16B segs)
            cpa16(su32(&sm->As[st][row][sg]), Ab + (size_t)row * DM + kb * 64 + sg);
            cpa16(su32(&sm->Bs[st][row][sg]), Wb + (size_t)row * DM + kb * 64 + sg);
        }
        CP_COMMIT;
    };

    issue(0, 0);

    for (int kb = 0; kb < DM / 64; kb++) {
        int st = kb & 1;
        if (kb + 1 < DM / 64) { issue(kb + 1, st ^ 1); CP_WAIT1; }
        else                  { CP_WAIT0; }
        __syncthreads();

#pragma unroll
        for (int ks = 0; ks < 4; ks++) {
            int kk = ks * 16;
            unsigned a[4][4], b[4][2];
#pragma unroll
            for (int mt = 0; mt < 4; mt++) {
                int r0 = wm + mt * 16;
                a[mt][0] = ldu(&sm->As[st][r0 + g    ][kk + 2*t    ]);
                a[mt][1] = ldu(&sm->As[st][r0 + g + 8][kk + 2*t    ]);
                a[mt][2] = ldu(&sm->As[st][r0 + g    ][kk + 2*t + 8]);
                a[mt][3] = ldu(&sm->As[st][r0 + g + 8][kk + 2*t + 8]);
            }
#pragma unroll
            for (int nt = 0; nt < 4; nt++) {
                int n0 = wn + nt * 8;
                b[nt][0] = ldu(&sm->Bs[st][n0 + g][kk + 2*t    ]);
                b[nt][1] = ldu(&sm->Bs[st][n0 + g][kk + 2*t + 8]);
            }
#pragma unroll
            for (int mt = 0; mt < 4; mt++)
#pragma unroll
                for (int nt = 0; nt < 4; nt++)
                    mma_f16(c[mt][nt], a[mt][0], a[mt][1], a[mt][2], a[mt][3],
                            b[nt][0], b[nt][1]);
        }
        __syncthreads();
    }

#pragma unroll
    for (int mt = 0; mt < 4; mt++) {
        int row0 = rowBase + wm + mt * 16 + g;
#pragma unroll
        for (int nt = 0; nt < 4; nt++) {
            int col = colBase + wn + nt * 8 + 2 * t;      // even
            float b0 = bias[col], b1 = bias[col + 1];
            float y0 = c[mt][nt][0] + b0, y1 = c[mt][nt][1] + b1;
            float z0 = c[mt][nt][2] + b0, z1 = c[mt][nt][3] + b1;
            if (do_rope) {
                int d = (col & 63) >> 1;
                float invf = powf(10000.0f, -(float)d / 32.0f);
                int n0 = row0 & (SEQ - 1);
                float s0, c0;
                sincosf((float)n0 * invf, &s0, &c0);
                float u0 = y0 * c0 - y1 * s0;
                float u1 = y0 * s0 + y1 * c0;
                y0 = u0; y1 = u1;
                float s1, c1;
                sincosf((float)(n0 + 8) * invf, &s1, &c1);
                float w0 = z0 * c1 - z1 * s1;
                float w1 = z0 * s1 + z1 * c1;
                z0 = w0; z1 = w1;
            }
            if (Cf) {
                float2 v0 = { y0, y1 };
                *(float2*)(Cf + (size_t)row0 * DM + col) = v0;
                float2 v1 = { z0, z1 };
                *(float2*)(Cf + (size_t)(row0 + 8) * DM + col) = v1;
            } else {
                *(__half2*)(Ch + (size_t)row0 * DM + col) = __floats2half2_rn(y0, y1);
                *(__half2*)(Ch + (size_t)(row0 + 8) * DM + col) = __floats2half2_rn(z0, z1);
            }
        }
    }
}

// ---------------------------------------------------------------------------
// Flash attention, fp16 MMA, cp.async 2-stage K/V pipeline.
// BQ=128, BK=64, Hd=64, 256 threads (8 warps). Warp w rows w*16..w*16+15.
// ---------------------------------------------------------------------------
#define AROW 72
struct ASmem {
    __half Qs[128][AROW];
    __half Ps[128][AROW];
    __half Ks[2][64][AROW];
    __half Vs[2][64][AROW];
};

__global__ __launch_bounds__(256) void attn_h(
    const __half* __restrict__ q, const __half* __restrict__ k,
    const __half* __restrict__ v, __half* __restrict__ o)
{
    extern __shared__ char sraw[];
    ASmem* sm = (ASmem*)sraw;

    const int tid = threadIdx.x;
    const int lane = tid & 31, warp = tid >> 5;
    const int g = lane >> 2, t = lane & 3;
    const int r0 = warp * 16;
    const int qt = blockIdx.x, h = blockIdx.y, b = blockIdx.z;

    const __half* qb = q + ((size_t)(b * SEQ + qt * 128)) * DM + h * HD;
    const __half* kb = k + (size_t)b * SEQ * DM + h * HD;
    const __half* vb = v + (size_t)b * SEQ * DM + h * HD;

    // Q tile: 128x64 (own cp.async group)
#pragma unroll
    for (int it = 0; it < 4; it++) {
        int idx = tid + it * 256;      // 0..1023
        int row = idx >> 3;            // 0..127
        int sg  = (idx & 7) << 3;
        cpa16(su32(&sm->Qs[row][sg]), qb + (size_t)row * DM + sg);
    }
    CP_COMMIT;

    auto issueKV = [&](int kt, int st) {
#pragma unroll
        for (int it = 0; it < 2; it++) {
            int idx = tid + it * 256;   // 0..511
            int row = idx >> 3;         // 0..63
            int sg  = (idx & 7) << 3;
            size_t off = (size_t)(kt * 64 + row) * DM + sg;
            cpa16(su32(&sm->Ks[st][row][sg]), kb + off);
            cpa16(su32(&sm->Vs[st][row][sg]), vb + off);
        }
        CP_COMMIT;
    };

    issueKV(0, 0);

    float m0 = -1e30f, m1 = -1e30f, l0 = 0.f, l1 = 0.f;
    float oacc[8][4];
#pragma unroll
    for (int nt = 0; nt < 8; nt++)
#pragma unroll
        for (int i = 0; i < 4; i++) oacc[nt][i] = 0.f;

    for (int kt = 0; kt < SEQ / 64; kt++) {
        int st = kt & 1;
        if (kt + 1 < SEQ / 64) { issueKV(kt + 1, st ^ 1); CP_WAIT1; }
        else                   { CP_WAIT0; }
        __syncthreads();

        // S = Q @ K^T  (scale post-MMA)
        float s[8][4];
#pragma unroll
        for (int nt = 0; nt < 8; nt++)
#pragma unroll
            for (int i = 0; i < 4; i++) s[nt][i] = 0.f;

#pragma unroll
        for (int ks = 0; ks < 4; ks++) {
            int kk = ks * 16;
            unsigned a0 = ldu(&sm->Qs[r0 + g    ][kk + 2*t    ]);
            unsigned a1 = ldu(&sm->Qs[r0 + g + 8][kk + 2*t    ]);
            unsigned a2 = ldu(&sm->Qs[r0 + g    ][kk + 2*t + 8]);
            unsigned a3 = ldu(&sm->Qs[r0 + g + 8][kk + 2*t + 8]);
#pragma unroll
            for (int nt = 0; nt < 8; nt++) {
                unsigned b0 = ldu(&sm->Ks[st][nt * 8 + g][kk + 2*t    ]);
                unsigned b1 = ldu(&sm->Ks[st][nt * 8 + g][kk + 2*t + 8]);
                mma_f16(s[nt], a0, a1, a2, a3, b0, b1);
            }
        }

        // Online softmax (rows g, g+8 of this warp's 16)
        float lm0 = -1e30f, lm1 = -1e30f;
#pragma unroll
        for (int nt = 0; nt < 8; nt++) {
#pragma unroll
            for (int i = 0; i < 4; i++) s[nt][i] *= 0.125f;
            lm0 = fmaxf(lm0, fmaxf(s[nt][0], s[nt][1]));
            lm1 = fmaxf(lm1, fmaxf(s[nt][2], s[nt][3]));
        }
#pragma unroll
        for (int off = 1; off <= 2; off <<= 1) {
            lm0 = fmaxf(lm0, __shfl_xor_sync(0xffffffffu, lm0, off));
            lm1 = fmaxf(lm1, __shfl_xor_sync(0xffffffffu, lm1, off));
        }
        float mn0 = fmaxf(m0, lm0), mn1 = fmaxf(m1, lm1);
        float sc0 = __expf(m0 - mn0), sc1 = __expf(m1 - mn1);
        m0 = mn0; m1 = mn1;

        float ll0 = 0.f, ll1 = 0.f;
#pragma unroll
        for (int nt = 0; nt < 8; nt++) {
            float p0 = __expf(s[nt][0] - mn0);
            float p1 = __expf(s[nt][1] - mn0);
            float p2 = __expf(s[nt][2] - mn1);
            float p3 = __expf(s[nt][3] - mn1);
            ll0 += p0 + p1;
            ll1 += p2 + p3;
            *(__half2*)&sm->Ps[r0 + g    ][nt * 8 + 2*t] = __floats2half2_rn(p0, p1);
            *(__half2*)&sm->Ps[r0 + g + 8][nt * 8 + 2*t] = __floats2half2_rn(p2, p3);
            oacc[nt][0] *= sc0; oacc[nt][1] *= sc0;
            oacc[nt][2] *= sc1; oacc[nt][3] *= sc1;
        }
#pragma unroll
        for (int off = 1; off <= 2; off <<= 1) {
            ll0 += __shfl_xor_sync(0xffffffffu, ll0, off);
            ll1 += __shfl_xor_sync(0xffffffffu, ll1, off);
        }
        l0 = l0 * sc0 + ll0;
        l1 = l1 * sc1 + ll1;
        __syncwarp();

        // O += P @ V   (V B-frag: cross-row half pairs via scalar LDS + pack)
#pragma unroll
        for (int ks = 0; ks < 4; ks++) {
            int kk = ks * 16;
            unsigned a0 = ldu(&sm->Ps[r0 + g    ][kk + 2*t    ]);
            unsigned a1 = ldu(&sm->Ps[r0 + g + 8][kk + 2*t    ]);
            unsigned a2 = ldu(&sm->Ps[r0 + g    ][kk + 2*t + 8]);
            unsigned a3 = ldu(&sm->Ps[r0 + g + 8][kk + 2*t + 8]);
#pragma unroll
            for (int nt = 0; nt < 8; nt++) {
                int n0 = nt * 8 + g;
                unsigned b0 = packh(sm->Vs[st][kk + 2*t    ][n0],
                                    sm->Vs[st][kk + 2*t + 1][n0]);
                unsigned b1 = packh(sm->Vs[st][kk + 2*t + 8][n0],
                                    sm->Vs[st][kk + 2*t + 9][n0]);
                mma_f16(oacc[nt], a0, a1, a2, a3, b0, b1);
            }
        }
        __syncthreads();   // stage reuse guard
    }

    float inv0 = 1.f / l0, inv1 = 1.f / l1;
    size_t rowg = (size_t)(b * SEQ + qt * 128 + r0 + g);
    __half* ob = o + rowg * DM + h * HD;
#pragma unroll
    for (int nt = 0; nt < 8; nt++) {
        *(__half2*)(ob + nt * 8 + 2*t) =
            __floats2half2_rn(oacc[nt][0] * inv0, oacc[nt][1] * inv0);
        *(__half2*)(ob + (size_t)8 * DM + nt * 8 + 2*t) =
            __floats2half2_rn(oacc[nt][2] * inv1, oacc[nt][3] * inv1);
    }
}

// ---------------------------------------------------------------------------

extern "C" void kernel_launch(void* const* d_in, const int* in_sizes, int n_in,
                              void* d_out, int out_size)
{
    const float* x  = (const float*)d_in[0];
    const float* wq = (const float*)d_in[1];
    const float* bq = (const float*)d_in[2];
    const float* wk = (const float*)d_in[3];
    const float* bk = (const float*)d_in[4];
    const float* wv = (const float*)d_in[5];
    const float* bv = (const float*)d_in[6];
    const float* wo = (const float*)d_in[7];
    const float* bo = (const float*)d_in[8];
    float* out = (float*)d_out;

    __half *xh, *wh, *q, *k, *v, *att;
    cudaGetSymbolAddress((void**)&xh,  g_xh);
    cudaGetSymbolAddress((void**)&wh,  g_wh);
    cudaGetSymbolAddress((void**)&q,   g_q);
    cudaGetSymbolAddress((void**)&k,   g_k);
    cudaGetSymbolAddress((void**)&v,   g_v);
    cudaGetSymbolAddress((void**)&att, g_att);
    __half* wqh = wh;
    __half* wkh = wh + (size_t)DM * DM;
    __half* wvh = wh + (size_t)2 * DM * DM;
    __half* woh = wh + (size_t)3 * DM * DM;

    // fp32 -> fp16 input conversion (RN)
    {
        int n8x = MROWS * DM / 8, n8w = DM * DM / 8;
        f2h<<<(n8x + 255) / 256, 256>>>(x, xh, n8x);
        f2h<<<(n8w + 255) / 256, 256>>>(wq, wqh, n8w);
        f2h<<<(n8w + 255) / 256, 256>>>(wk, wkh, n8w);
        f2h<<<(n8w + 255) / 256, 256>>>(wv, wvh, n8w);
        f2h<<<(n8w + 255) / 256, 256>>>(wo, woh, n8w);
    }

    int gsm = (int)sizeof(GSmem);    // 73,728 B
    cudaFuncSetAttribute(hgemm, cudaFuncAttributeMaxDynamicSharedMemorySize, gsm);
    int asm_ = (int)sizeof(ASmem);   // 73,728 B
    cudaFuncSetAttribute(attn_h, cudaFuncAttributeMaxDynamicSharedMemorySize, asm_);

    dim3 gg(DM / 128, MROWS / 128);
    hgemm<<<gg, 256, gsm>>>(xh, wqh, bq, q, nullptr, 1);   // fused RoPE
    hgemm<<<gg, 256, gsm>>>(xh, wkh, bk, k, nullptr, 1);   // fused RoPE
    hgemm<<<gg, 256, gsm>>>(xh, wvh, bv, v, nullptr, 0);

    attn_h<<<dim3(SEQ / 128, NH, BATCH), 256, asm_>>>(q, k, v, att);

    hgemm<<<gg, 256, gsm>>>(att, woh, bo, nullptr, out, 0);
}

// round 10
// speedup vs baseline: 14.1690x; 1.1451x over previous
#include <cuda_runtime.h>
#include <cuda_fp16.h>
#include <math.h>
#include <stdint.h>

#define BATCH 4
#define SEQ   2048
#define DM    1024
#define NH    16
#define HD    64
#define MROWS (BATCH*SEQ)

// Scratch (device-global; no allocation allowed)
__device__ __half g_xh[MROWS*DM];
__device__ __half g_wh[4][DM*DM];
__device__ __half g_q[MROWS*DM];
__device__ __half g_k[MROWS*DM];
__device__ __half g_v[MROWS*DM];
__device__ __half g_att[MROWS*DM];

// ---------------------------------------------------------------------------
// helpers
// ---------------------------------------------------------------------------
__device__ __forceinline__ uint32_t su32(const void* p) {
    return (uint32_t)__cvta_generic_to_shared(p);
}
__device__ __forceinline__ void cpa16(uint32_t dst, const void* src) {
    asm volatile("cp.async.cg.shared.global [%0], [%1], 16;" :: "r"(dst), "l"(src));
}
#define CP_COMMIT asm volatile("cp.async.commit_group;" ::: "memory")
#define CP_WAIT1  asm volatile("cp.async.wait_group 1;" ::: "memory")
#define CP_WAIT0  asm volatile("cp.async.wait_group 0;" ::: "memory")

__device__ __forceinline__ void mma_f16(float c[4],
    unsigned a0, unsigned a1, unsigned a2, unsigned a3,
    unsigned b0, unsigned b1)
{
    asm volatile(
        "mma.sync.aligned.m16n8k16.row.col.f32.f16.f16.f32 "
        "{%0,%1,%2,%3}, {%4,%5,%6,%7}, {%8,%9}, {%0,%1,%2,%3};"
        : "+f"(c[0]), "+f"(c[1]), "+f"(c[2]), "+f"(c[3])
        : "r"(a0), "r"(a1), "r"(a2), "r"(a3), "r"(b0), "r"(b1));
}

__device__ __forceinline__ void ldsm4(unsigned& r0, unsigned& r1,
                                      unsigned& r2, unsigned& r3, uint32_t addr)
{
    asm volatile("ldmatrix.sync.aligned.m8n8.x4.shared.b16 {%0,%1,%2,%3}, [%4];"
                 : "=r"(r0), "=r"(r1), "=r"(r2), "=r"(r3) : "r"(addr));
}
__device__ __forceinline__ void ldsm4t(unsigned& r0, unsigned& r1,
                                       unsigned& r2, unsigned& r3, uint32_t addr)
{
    asm volatile("ldmatrix.sync.aligned.m8n8.x4.trans.shared.b16 {%0,%1,%2,%3}, [%4];"
                 : "=r"(r0), "=r"(r1), "=r"(r2), "=r"(r3) : "r"(addr));
}

// ---------------------------------------------------------------------------
// fp32 -> fp16 convert (RN), all 5 tensors in one launch.
// ---------------------------------------------------------------------------
__global__ void f2h_all(const float* __restrict__ x,
                        const float* __restrict__ w0, const float* __restrict__ w1,
                        const float* __restrict__ w2, const float* __restrict__ w3,
                        __half* __restrict__ xh, __half* __restrict__ wh,
                        int nx8, int nw8)
{
    int i = blockIdx.x * blockDim.x + threadIdx.x;
    const float* src; __half* dst; int off;
    if (i < nx8)                { src = x;  dst = xh; off = i; }
    else {
        int j = i - nx8;
        int seg = j / nw8; off = j % nw8;
        const float* ws[4] = { w0, w1, w2, w3 };
        if (seg >= 4) return;
        src = ws[seg]; dst = wh + (size_t)seg * DM * DM;
    }
    float4 v0 = ((const float4*)src)[2*off];
    float4 v1 = ((const float4*)src)[2*off + 1];
    __half2 h0 = __floats2half2_rn(v0.x, v0.y);
    __half2 h1 = __floats2half2_rn(v0.z, v0.w);
    __half2 h2 = __floats2half2_rn(v1.x, v1.y);
    __half2 h3 = __floats2half2_rn(v1.z, v1.w);
    uint4 o = { *(unsigned*)&h0, *(unsigned*)&h1, *(unsigned*)&h2, *(unsigned*)&h3 };
    ((uint4*)dst)[off] = o;
}

// ---------------------------------------------------------------------------
// GEMM: C[M,N] = A[M,K] @ W[N,K]^T + bias[N]   (fp16 MMA, f32 accum, LDSM)
// 128x128 tile, BK=64, 256 threads (8 warps), warp tile 64x32, cp.async 2-stage.
// ---------------------------------------------------------------------------
#define GROW 72
struct GSmem { __half As[2][128][GROW]; __half Bs[2][128][GROW]; };

__global__ __launch_bounds__(256) void hgemm(
    const __half* __restrict__ A, const __half* __restrict__ W,
    const float* __restrict__ bias, __half* __restrict__ Ch,
    float* __restrict__ Cf, int do_rope)
{
    extern __shared__ char sraw[];
    GSmem* sm = (GSmem*)sraw;

    const int tid = threadIdx.x;
    const int lane = tid & 31, warp = tid >> 5;
    const int g = lane >> 2, t = lane & 3;
    const int wm = (warp & 1) * 64;
    const int wn = (warp >> 1) * 32;
    const int rowBase = blockIdx.y * 128;
    const int colBase = blockIdx.x * 128;
    const __half* Ab = A + (size_t)rowBase * DM;
    const __half* Wb = W + (size_t)colBase * DM;

    const int l15 = lane & 15, lhi = lane >> 4;          // x4 A-style
    const int bq = lane & 7, bb = (lane >> 3) & 3;       // x4 B-style (2 nt)

    float c[4][4][4];
#pragma unroll
    for (int mt = 0; mt < 4; mt++)
#pragma unroll
        for (int nt = 0; nt < 4; nt++)
#pragma unroll
            for (int i = 0; i < 4; i++) c[mt][nt][i] = 0.f;

    auto issue = [&](int kb, int st) {
#pragma unroll
        for (int it = 0; it < 4; it++) {
            int idx = tid + it * 256;       // 0..1023
            int row = idx >> 3;             // 0..127
            int sg  = (idx & 7) << 3;       // 0,8,..,56 halves
            cpa16(su32(&sm->As[st][row][sg]), Ab + (size_t)row * DM + kb * 64 + sg);
            cpa16(su32(&sm->Bs[st][row][sg]), Wb + (size_t)row * DM + kb * 64 + sg);
        }
        CP_COMMIT;
    };

    issue(0, 0);

    for (int kb = 0; kb < DM / 64; kb++) {
        int st = kb & 1;
        if (kb + 1 < DM / 64) { issue(kb + 1, st ^ 1); CP_WAIT1; }
        else                  { CP_WAIT0; }
        __syncthreads();

#pragma unroll
        for (int ks = 0; ks < 4; ks++) {
            int kk = ks * 16;
            unsigned a[4][4], b[4][2];
#pragma unroll
            for (int mt = 0; mt < 4; mt++)
                ldsm4(a[mt][0], a[mt][1], a[mt][2], a[mt][3],
                      su32(&sm->As[st][wm + mt * 16 + l15][kk + lhi * 8]));
#pragma unroll
            for (int np = 0; np < 2; np++)   // nt pairs (0,1) and (2,3)
                ldsm4(b[2*np][0], b[2*np][1], b[2*np+1][0], b[2*np+1][1],
                      su32(&sm->Bs[st][wn + np * 16 + (bb >> 1) * 8 + bq][kk + (bb & 1) * 8]));
#pragma unroll
            for (int mt = 0; mt < 4; mt++)
#pragma unroll
                for (int nt = 0; nt < 4; nt++)
                    mma_f16(c[mt][nt], a[mt][0], a[mt][1], a[mt][2], a[mt][3],
                            b[nt][0], b[nt][1]);
        }
        __syncthreads();
    }

#pragma unroll
    for (int mt = 0; mt < 4; mt++) {
        int row0 = rowBase + wm + mt * 16 + g;
#pragma unroll
        for (int nt = 0; nt < 4; nt++) {
            int col = colBase + wn + nt * 8 + 2 * t;      // even
            float b0 = bias[col], b1 = bias[col + 1];
            float y0 = c[mt][nt][0] + b0, y1 = c[mt][nt][1] + b1;
            float z0 = c[mt][nt][2] + b0, z1 = c[mt][nt][3] + b1;
            if (do_rope) {
                int d = (col & 63) >> 1;
                float invf = powf(10000.0f, -(float)d / 32.0f);
                int n0 = row0 & (SEQ - 1);
                float s0, c0;
                sincosf((float)n0 * invf, &s0, &c0);
                float u0 = y0 * c0 - y1 * s0;
                float u1 = y0 * s0 + y1 * c0;
                y0 = u0; y1 = u1;
                float s1, c1;
                sincosf((float)(n0 + 8) * invf, &s1, &c1);
                float w0 = z0 * c1 - z1 * s1;
                float w1 = z0 * s1 + z1 * c1;
                z0 = w0; z1 = w1;
            }
            if (Cf) {
                float2 v0 = { y0, y1 };
                *(float2*)(Cf + (size_t)row0 * DM + col) = v0;
                float2 v1 = { z0, z1 };
                *(float2*)(Cf + (size_t)(row0 + 8) * DM + col) = v1;
            } else {
                *(__half2*)(Ch + (size_t)row0 * DM + col) = __floats2half2_rn(y0, y1);
                *(__half2*)(Ch + (size_t)(row0 + 8) * DM + col) = __floats2half2_rn(z0, z1);
            }
        }
    }
}

// ---------------------------------------------------------------------------
// Flash attention, fp16 MMA + LDSM (V via ldmatrix.trans), cp.async 2-stage.
// BQ=128, BK=64, Hd=64, 256 threads (8 warps). Warp w rows w*16..w*16+15.
// ---------------------------------------------------------------------------
#define AROW 72
struct ASmem {
    __half Qs[128][AROW];
    __half Ps[128][AROW];
    __half Ks[2][64][AROW];
    __half Vs[2][64][AROW];
};

__global__ __launch_bounds__(256) void attn_h(
    const __half* __restrict__ q, const __half* __restrict__ k,
    const __half* __restrict__ v, __half* __restrict__ o)
{
    extern __shared__ char sraw[];
    ASmem* sm = (ASmem*)sraw;

    const int tid = threadIdx.x;
    const int lane = tid & 31, warp = tid >> 5;
    const int g = lane >> 2, t = lane & 3;
    const int r0 = warp * 16;
    const int qt = blockIdx.x, h = blockIdx.y, b = blockIdx.z;

    const int l15 = lane & 15, lhi = lane >> 4;      // x4 A-style
    const int bq = lane & 7, bb = (lane >> 3) & 3;   // x4 B-style

    const __half* qb = q + ((size_t)(b * SEQ + qt * 128)) * DM + h * HD;
    const __half* kb = k + (size_t)b * SEQ * DM + h * HD;
    const __half* vb = v + (size_t)b * SEQ * DM + h * HD;

    // Q tile: 128x64 (own cp.async group)
#pragma unroll
    for (int it = 0; it < 4; it++) {
        int idx = tid + it * 256;      // 0..1023
        int row = idx >> 3;            // 0..127
        int sg  = (idx & 7) << 3;
        cpa16(su32(&sm->Qs[row][sg]), qb + (size_t)row * DM + sg);
    }
    CP_COMMIT;

    auto issueKV = [&](int kt, int st) {
#pragma unroll
        for (int it = 0; it < 2; it++) {
            int idx = tid + it * 256;   // 0..511
            int row = idx >> 3;         // 0..63
            int sg  = (idx & 7) << 3;
            size_t off = (size_t)(kt * 64 + row) * DM + sg;
            cpa16(su32(&sm->Ks[st][row][sg]), kb + off);
            cpa16(su32(&sm->Vs[st][row][sg]), vb + off);
        }
        CP_COMMIT;
    };

    issueKV(0, 0);

    float m0 = -1e30f, m1 = -1e30f, l0 = 0.f, l1 = 0.f;
    float oacc[8][4];
#pragma unroll
    for (int nt = 0; nt < 8; nt++)
#pragma unroll
        for (int i = 0; i < 4; i++) oacc[nt][i] = 0.f;

    for (int kt = 0; kt < SEQ / 64; kt++) {
        int st = kt & 1;
        if (kt + 1 < SEQ / 64) { issueKV(kt + 1, st ^ 1); CP_WAIT1; }
        else                   { CP_WAIT0; }
        __syncthreads();

        // S = Q @ K^T  (scale post-MMA)
        float s[8][4];
#pragma unroll
        for (int nt = 0; nt < 8; nt++)
#pragma unroll
            for (int i = 0; i < 4; i++) s[nt][i] = 0.f;

#pragma unroll
        for (int ks = 0; ks < 4; ks++) {
            int kk = ks * 16;
            unsigned a0, a1, a2, a3;
            ldsm4(a0, a1, a2, a3, su32(&sm->Qs[r0 + l15][kk + lhi * 8]));
            unsigned bK[8][2];
#pragma unroll
            for (int np = 0; np < 4; np++)
                ldsm4(bK[2*np][0], bK[2*np][1], bK[2*np+1][0], bK[2*np+1][1],
                      su32(&sm->Ks[st][np * 16 + (bb >> 1) * 8 + bq][kk + (bb & 1) * 8]));
#pragma unroll
            for (int nt = 0; nt < 8; nt++)
                mma_f16(s[nt], a0, a1, a2, a3, bK[nt][0], bK[nt][1]);
        }

        // Online softmax (rows g, g+8 of this warp's 16)
        float lm0 = -1e30f, lm1 = -1e30f;
#pragma unroll
        for (int nt = 0; nt < 8; nt++) {
#pragma unroll
            for (int i = 0; i < 4; i++) s[nt][i] *= 0.125f;
            lm0 = fmaxf(lm0, fmaxf(s[nt][0], s[nt][1]));
            lm1 = fmaxf(lm1, fmaxf(s[nt][2], s[nt][3]));
        }
#pragma unroll
        for (int off = 1; off <= 2; off <<= 1) {
            lm0 = fmaxf(lm0, __shfl_xor_sync(0xffffffffu, lm0, off));
            lm1 = fmaxf(lm1, __shfl_xor_sync(0xffffffffu, lm1, off));
        }
        float mn0 = fmaxf(m0, lm0), mn1 = fmaxf(m1, lm1);
        float sc0 = __expf(m0 - mn0), sc1 = __expf(m1 - mn1);
        m0 = mn0; m1 = mn1;

        float ll0 = 0.f, ll1 = 0.f;
#pragma unroll
        for (int nt = 0; nt < 8; nt++) {
            float p0 = __expf(s[nt][0] - mn0);
            float p1 = __expf(s[nt][1] - mn0);
            float p2 = __expf(s[nt][2] - mn1);
            float p3 = __expf(s[nt][3] - mn1);
            ll0 += p0 + p1;
            ll1 += p2 + p3;
            *(__half2*)&sm->Ps[r0 + g    ][nt * 8 + 2*t] = __floats2half2_rn(p0, p1);
            *(__half2*)&sm->Ps[r0 + g + 8][nt * 8 + 2*t] = __floats2half2_rn(p2, p3);
            oacc[nt][0] *= sc0; oacc[nt][1] *= sc0;
            oacc[nt][2] *= sc1; oacc[nt][3] *= sc1;
        }
#pragma unroll
        for (int off = 1; off <= 2; off <<= 1) {
            ll0 += __shfl_xor_sync(0xffffffffu, ll0, off);
            ll1 += __shfl_xor_sync(0xffffffffu, ll1, off);
        }
        l0 = l0 * sc0 + ll0;
        l1 = l1 * sc1 + ll1;
        __syncwarp();

        // O += P @ V   (V B-frags via ldmatrix.trans, 2 nt per x4)
#pragma unroll
        for (int ks = 0; ks < 4; ks++) {
            int kk = ks * 16;
            unsigned a0, a1, a2, a3;
            ldsm4(a0, a1, a2, a3, su32(&sm->Ps[r0 + l15][kk + lhi * 8]));
            unsigned bV[8][2];
#pragma unroll
            for (int np = 0; np < 4; np++)
                ldsm4t(bV[2*np][0], bV[2*np][1], bV[2*np+1][0], bV[2*np+1][1],
                       su32(&sm->Vs[st][kk + ((bb & 1) ? 8 : 0) + bq][np * 16 + (bb >> 1) * 8]));
#pragma unroll
            for (int nt = 0; nt < 8; nt++)
                mma_f16(oacc[nt], a0, a1, a2, a3, bV[nt][0], bV[nt][1]);
        }
        __syncthreads();   // stage reuse guard
    }

    float inv0 = 1.f / l0, inv1 = 1.f / l1;
    size_t rowg = (size_t)(b * SEQ + qt * 128 + r0 + g);
    __half* ob = o + rowg * DM + h * HD;
#pragma unroll
    for (int nt = 0; nt < 8; nt++) {
        *(__half2*)(ob + nt * 8 + 2*t) =
            __floats2half2_rn(oacc[nt][0] * inv0, oacc[nt][1] * inv0);
        *(__half2*)(ob + (size_t)8 * DM + nt * 8 + 2*t) =
            __floats2half2_rn(oacc[nt][2] * inv1, oacc[nt][3] * inv1);
    }
}

// ---------------------------------------------------------------------------

extern "C" void kernel_launch(void* const* d_in, const int* in_sizes, int n_in,
                              void* d_out, int out_size)
{
    const float* x  = (const float*)d_in[0];
    const float* wq = (const float*)d_in[1];
    const float* bq = (const float*)d_in[2];
    const float* wk = (const float*)d_in[3];
    const float* bk = (const float*)d_in[4];
    const float* wv = (const float*)d_in[5];
    const float* bv = (const float*)d_in[6];
    const float* wo = (const float*)d_in[7];
    const float* bo = (const float*)d_in[8];
    float* out = (float*)d_out;

    __half *xh, *wh, *q, *k, *v, *att;
    cudaGetSymbolAddress((void**)&xh,  g_xh);
    cudaGetSymbolAddress((void**)&wh,  g_wh);
    cudaGetSymbolAddress((void**)&q,   g_q);
    cudaGetSymbolAddress((void**)&k,   g_k);
    cudaGetSymbolAddress((void**)&v,   g_v);
    cudaGetSymbolAddress((void**)&att, g_att);
    __half* wqh = wh;
    __half* wkh = wh + (size_t)DM * DM;
    __half* wvh = wh + (size_t)2 * DM * DM;
    __half* woh = wh + (size_t)3 * DM * DM;

    // fp32 -> fp16 input conversion (RN), single launch
    {
        int nx8 = MROWS * DM / 8, nw8 = DM * DM / 8;
        int tot = nx8 + 4 * nw8;
        f2h_all<<<(tot + 255) / 256, 256>>>(x, wq, wk, wv, wo, xh, wh, nx8, nw8);
    }

    int gsm = (int)sizeof(GSmem);    // 73,728 B
    cudaFuncSetAttribute(hgemm, cudaFuncAttributeMaxDynamicSharedMemorySize, gsm);
    int asm_ = (int)sizeof(ASmem);   // 73,728 B
    cudaFuncSetAttribute(attn_h, cudaFuncAttributeMaxDynamicSharedMemorySize, asm_);

    dim3 gg(DM / 128, MROWS / 128);
    hgemm<<<gg, 256, gsm>>>(xh, wqh, bq, q, nullptr, 1);   // fused RoPE
    hgemm<<<gg, 256, gsm>>>(xh, wkh, bk, k, nullptr, 1);   // fused RoPE
    hgemm<<<gg, 256, gsm>>>(xh, wvh, bv, v, nullptr, 0);

    attn_h<<<dim3(SEQ / 128, NH, BATCH), 256, asm_>>>(q, k, v, att);

    hgemm<<<gg, 256, gsm>>>(att, woh, bo, nullptr, out, 0);
}